// round 1
// baseline (speedup 1.0000x reference)
#include <cuda_runtime.h>

#define N_NODES 200000
#define D       128
#define N1      81920
#define BATCH   8192
#define KNB     10
#define TM      64          // rows per block
#define NTHREADS 256

// ---------------- device-global scratch (allocation-free rule) ----------------
__device__ float g_h1[(size_t)N1 * D];          // layer-1 embeddings, 41.9 MB
__device__ float g_Wt[2][2 * D][D];             // transposed weights [layer][d][j]

// ---------------- weight transpose: W[j][d] -> g_Wt[l][d][j] ----------------
__global__ void transpose_w_kernel(const float* __restrict__ W1,
                                   const float* __restrict__ W2) {
    int total = D * 2 * D;                      // 32768 per matrix
    for (int i = blockIdx.x * blockDim.x + threadIdx.x; i < total;
         i += gridDim.x * blockDim.x) {
        int j = i / (2 * D);
        int d = i % (2 * D);
        g_Wt[0][d][j] = W1[i];
        g_Wt[1][d][j] = W2[i];
    }
}

// ---------------- fused SAGE layer: gather + mean-agg + GEMM + ReLU ----------
// smem: Ws [256][128] f32 (128 KB)  +  comb [TM][256] f32 (64 KB) = 192 KB
template <int LAYER>
__global__ __launch_bounds__(NTHREADS, 1)
void sage_layer_kernel(const float* __restrict__ feats_in,
                       const int*   __restrict__ self_idx,
                       const int*   __restrict__ neigh_idx,
                       float*       __restrict__ out_ext) {
    extern __shared__ float smem[];
    float* Ws   = smem;                 // [2D][D] = 32768 floats
    float* comb = smem + 2 * D * D;     // [TM][2D] = 16384 floats

    const float* feats = (LAYER == 1) ? feats_in : g_h1;
    float*       out   = (LAYER == 1) ? g_h1 : out_ext;
    const float* Wg    = &g_Wt[LAYER - 1][0][0];

    const int t = threadIdx.x;

    // ---- stage transposed weights (coalesced float4 copy, L2-hot) ----
    {
        const float4* src = (const float4*)Wg;
        float4*       dst = (float4*)Ws;
        #pragma unroll
        for (int i = 0; i < (2 * D * D) / 4 / NTHREADS; i++)
            dst[i * NTHREADS + t] = src[i * NTHREADS + t];
    }

    // ---- gather phase: build comb[r] = [self(128) | mean_agg(128)] ----
    {
        const int d    = t & (D - 1);       // 0..127
        const int half = t >> 7;            // 0 or 1
        for (int r = half; r < TM; r += 2) {
            const int row  = blockIdx.x * TM + r;
            const int nsel = self_idx[row];
            int nn[KNB];
            #pragma unroll
            for (int k = 0; k < KNB; k++)
                nn[k] = neigh_idx[row * KNB + k];
            float s = feats[(size_t)nsel * D + d];
            float acc = 0.0f;
            #pragma unroll
            for (int k = 0; k < KNB; k++)
                acc += feats[(size_t)nn[k] * D + d];
            comb[r * (2 * D) + d]     = s;
            comb[r * (2 * D) + D + d] = acc * (1.0f / (float)KNB);
        }
    }
    __syncthreads();

    // ---- GEMM: out[row][j] = relu( sum_d comb[row][d] * Wt[d][j] ) ----
    const int lane  = t & 31;
    const int warp  = t >> 5;               // 8 warps -> 8 row-groups of 8
    const int rbase = warp * 8;
    const float4* WsV = (const float4*)Ws;  // Ws[d][j]: row d = 32 float4

    float acc[8][4];
    #pragma unroll
    for (int r = 0; r < 8; r++)
        #pragma unroll
        for (int c = 0; c < 4; c++) acc[r][c] = 0.0f;

    #pragma unroll 4
    for (int d = 0; d < 2 * D; d += 4) {
        float4 w0 = WsV[(d + 0) * 32 + lane];
        float4 w1 = WsV[(d + 1) * 32 + lane];
        float4 w2 = WsV[(d + 2) * 32 + lane];
        float4 w3 = WsV[(d + 3) * 32 + lane];
        #pragma unroll
        for (int r = 0; r < 8; r++) {
            float4 c4 = *(const float4*)&comb[(rbase + r) * (2 * D) + d];
            acc[r][0] += c4.x * w0.x; acc[r][1] += c4.x * w0.y;
            acc[r][2] += c4.x * w0.z; acc[r][3] += c4.x * w0.w;
            acc[r][0] += c4.y * w1.x; acc[r][1] += c4.y * w1.y;
            acc[r][2] += c4.y * w1.z; acc[r][3] += c4.y * w1.w;
            acc[r][0] += c4.z * w2.x; acc[r][1] += c4.z * w2.y;
            acc[r][2] += c4.z * w2.z; acc[r][3] += c4.z * w2.w;
            acc[r][0] += c4.w * w3.x; acc[r][1] += c4.w * w3.y;
            acc[r][2] += c4.w * w3.z; acc[r][3] += c4.w * w3.w;
        }
    }

    // ---- epilogue: ReLU + coalesced float4 store ----
    #pragma unroll
    for (int r = 0; r < 8; r++) {
        const int row = blockIdx.x * TM + rbase + r;
        float4 o;
        o.x = fmaxf(acc[r][0], 0.0f);
        o.y = fmaxf(acc[r][1], 0.0f);
        o.z = fmaxf(acc[r][2], 0.0f);
        o.w = fmaxf(acc[r][3], 0.0f);
        *(float4*)&out[(size_t)row * D + lane * 4] = o;
    }
}

// ---------------- launch ----------------
extern "C" void kernel_launch(void* const* d_in, const int* in_sizes, int n_in,
                              void* d_out, int out_size) {
    const float* raw_features = (const float*)d_in[0];
    const float* W1           = (const float*)d_in[1];
    const float* W2           = (const float*)d_in[2];
    const int*   layer1_nodes = (const int*)d_in[3];
    const int*   neigh0_idx   = (const int*)d_in[4];
    const int*   map_batch    = (const int*)d_in[5];
    const int*   neigh1_idx   = (const int*)d_in[6];
    float*       out          = (float*)d_out;

    const int smem_bytes = (2 * D * D + TM * 2 * D) * (int)sizeof(float); // 192 KB
    cudaFuncSetAttribute(sage_layer_kernel<1>,
                         cudaFuncAttributeMaxDynamicSharedMemorySize, smem_bytes);
    cudaFuncSetAttribute(sage_layer_kernel<2>,
                         cudaFuncAttributeMaxDynamicSharedMemorySize, smem_bytes);

    transpose_w_kernel<<<32, NTHREADS>>>(W1, W2);
    sage_layer_kernel<1><<<N1 / TM, NTHREADS, smem_bytes>>>(
        raw_features, layer1_nodes, neigh0_idx, nullptr);
    sage_layer_kernel<2><<<BATCH / TM, NTHREADS, smem_bytes>>>(
        nullptr, map_batch, neigh1_idx, out);
}

// round 2
// speedup vs baseline: 1.4505x; 1.4505x over previous
#include <cuda_runtime.h>

#define N_NODES 200000
#define D       128
#define N1      81920
#define BATCH   8192
#define KNB     10
#define TM      64          // rows per block
#define NTHREADS 256
#define WS_STRIDE 132       // padded floats per Ws row (33 float4, conflict-free)

// ---------------- device-global scratch (allocation-free rule) ----------------
__device__ float g_h1[(size_t)N1 * D];          // layer-1 embeddings, 41.9 MB

// ---------------- fused SAGE layer: gather + mean-agg + GEMM + ReLU ----------
// smem: Ws [256][132] f32 (132 KB)  +  comb [TM][256] f32 (64 KB) = ~199 KB
template <int LAYER>
__global__ __launch_bounds__(NTHREADS, 1)
void sage_layer_kernel(const float* __restrict__ feats_in,
                       const float* __restrict__ Wg,
                       const int*   __restrict__ self_idx,
                       const int*   __restrict__ neigh_idx,
                       float*       __restrict__ out_ext) {
    extern __shared__ float smem[];
    float* Ws   = smem;                         // [2D][WS_STRIDE]
    float* comb = smem + 2 * D * WS_STRIDE;     // [TM][2D], warp-private 8-row slabs

    const float* feats = (LAYER == 1) ? feats_in : g_h1;
    float*       out   = (LAYER == 1) ? g_h1 : out_ext;

    const int t    = threadIdx.x;
    const int lane = t & 31;
    const int warp = t >> 5;                    // 8 warps, 8 rows each

    // ---- stage W transposed: Ws[d][j] = W[j][d]  (coalesced float4 gmem read) ----
    {
        // 2D*D = 32768 floats = 8192 float4; 256 threads -> 32 iters
        const float4* src = (const float4*)Wg;
        #pragma unroll
        for (int i = 0; i < (2 * D * D) / 4 / NTHREADS; i++) {
            int idx = i * NTHREADS + t;          // float4 index into W[j][d]
            int j   = idx >> 6;                  // idx / (2D/4)
            int d4  = idx & 63;                  // float4 within row -> d = 4*d4
            float4 v = src[idx];
            Ws[(4 * d4 + 0) * WS_STRIDE + j] = v.x;
            Ws[(4 * d4 + 1) * WS_STRIDE + j] = v.y;
            Ws[(4 * d4 + 2) * WS_STRIDE + j] = v.z;
            Ws[(4 * d4 + 3) * WS_STRIDE + j] = v.w;
        }
    }
    __syncthreads();

    // ---- per-warp gather: comb slab [8][256] = [self(128)|mean_agg(128)] ----
    float* cwarp = comb + warp * 8 * (2 * D);
    {
        #pragma unroll 2
        for (int r = 0; r < 8; r++) {
            const int row  = blockIdx.x * TM + warp * 8 + r;
            const int nsel = __ldg(&self_idx[row]);
            float4 s = __ldg((const float4*)&feats[(size_t)nsel * D] + lane);
            float4 a = make_float4(0.f, 0.f, 0.f, 0.f);
            #pragma unroll
            for (int k = 0; k < KNB; k++) {
                const int nk = __ldg(&neigh_idx[row * KNB + k]);
                float4 f = __ldg((const float4*)&feats[(size_t)nk * D] + lane);
                a.x += f.x; a.y += f.y; a.z += f.z; a.w += f.w;
            }
            const float inv = 1.0f / (float)KNB;
            a.x *= inv; a.y *= inv; a.z *= inv; a.w *= inv;
            *(float4*)&cwarp[r * (2 * D) + 4 * lane]     = s;
            *(float4*)&cwarp[r * (2 * D) + D + 4 * lane] = a;
        }
    }
    __syncwarp();

    // ---- warp-local GEMM: out[row][j] = relu( sum_d comb[row][d] * Ws[d][j] ) ----
    const float4* WsV = (const float4*)Ws;      // row stride = 33 float4

    float acc[8][4];
    #pragma unroll
    for (int r = 0; r < 8; r++)
        #pragma unroll
        for (int c = 0; c < 4; c++) acc[r][c] = 0.0f;

    #pragma unroll 4
    for (int d = 0; d < 2 * D; d += 4) {
        float4 w0 = WsV[(d + 0) * 33 + lane];
        float4 w1 = WsV[(d + 1) * 33 + lane];
        float4 w2 = WsV[(d + 2) * 33 + lane];
        float4 w3 = WsV[(d + 3) * 33 + lane];
        #pragma unroll
        for (int r = 0; r < 8; r++) {
            float4 c4 = *(const float4*)&cwarp[r * (2 * D) + d];
            acc[r][0] += c4.x * w0.x; acc[r][1] += c4.x * w0.y;
            acc[r][2] += c4.x * w0.z; acc[r][3] += c4.x * w0.w;
            acc[r][0] += c4.y * w1.x; acc[r][1] += c4.y * w1.y;
            acc[r][2] += c4.y * w1.z; acc[r][3] += c4.y * w1.w;
            acc[r][0] += c4.z * w2.x; acc[r][1] += c4.z * w2.y;
            acc[r][2] += c4.z * w2.z; acc[r][3] += c4.z * w2.w;
            acc[r][0] += c4.w * w3.x; acc[r][1] += c4.w * w3.y;
            acc[r][2] += c4.w * w3.z; acc[r][3] += c4.w * w3.w;
        }
    }

    // ---- epilogue: ReLU + coalesced float4 store ----
    #pragma unroll
    for (int r = 0; r < 8; r++) {
        const int row = blockIdx.x * TM + warp * 8 + r;
        float4 o;
        o.x = fmaxf(acc[r][0], 0.0f);
        o.y = fmaxf(acc[r][1], 0.0f);
        o.z = fmaxf(acc[r][2], 0.0f);
        o.w = fmaxf(acc[r][3], 0.0f);
        *(float4*)&out[(size_t)row * D + lane * 4] = o;
    }
}

// ---------------- launch ----------------
extern "C" void kernel_launch(void* const* d_in, const int* in_sizes, int n_in,
                              void* d_out, int out_size) {
    const float* raw_features = (const float*)d_in[0];
    const float* W1           = (const float*)d_in[1];
    const float* W2           = (const float*)d_in[2];
    const int*   layer1_nodes = (const int*)d_in[3];
    const int*   neigh0_idx   = (const int*)d_in[4];
    const int*   map_batch    = (const int*)d_in[5];
    const int*   neigh1_idx   = (const int*)d_in[6];
    float*       out          = (float*)d_out;

    const int smem_bytes = (2 * D * WS_STRIDE + TM * 2 * D) * (int)sizeof(float);
    static bool attr_set = false;
    cudaFuncSetAttribute(sage_layer_kernel<1>,
                         cudaFuncAttributeMaxDynamicSharedMemorySize, smem_bytes);
    cudaFuncSetAttribute(sage_layer_kernel<2>,
                         cudaFuncAttributeMaxDynamicSharedMemorySize, smem_bytes);
    (void)attr_set;

    sage_layer_kernel<1><<<N1 / TM, NTHREADS, smem_bytes>>>(
        raw_features, W1, layer1_nodes, neigh0_idx, nullptr);
    sage_layer_kernel<2><<<BATCH / TM, NTHREADS, smem_bytes>>>(
        nullptr, W2, map_batch, neigh1_idx, out);
}

// round 5
// speedup vs baseline: 1.8941x; 1.3058x over previous
#include <cuda_runtime.h>

#define N_NODES 200000
#define D       128
#define N1      81920
#define BATCH   8192
#define KNB     10
#define TM      64          // rows per block
#define NTHREADS 256
#define W2_STRIDE 130       // float2 per d-pair row (padded)

// ---------------- device-global scratch (allocation-free rule) ----------------
__device__ float g_h1[(size_t)N1 * D];          // layer-1 embeddings, 41.9 MB

// packed f32x2 FMA: acc = a*b + acc (two independent fp32 lanes)
__device__ __forceinline__ void fma_f32x2(unsigned long long& acc,
                                          unsigned long long a,
                                          unsigned long long b) {
    asm("fma.rn.f32x2 %0, %1, %2, %0;" : "+l"(acc) : "l"(a), "l"(b));
}

// ---------------- fused SAGE layer: gather + mean-agg + GEMM(FFMA2) + ReLU ----
// smem: Ws2 [128 d-pairs][130 float2] (~133 KB) + comb [TM][2D] f32 (64 KB)
template <int LAYER>
__global__ __launch_bounds__(NTHREADS, 1)
void sage_layer_kernel(const float* __restrict__ feats_in,
                       const float* __restrict__ Wg,
                       const int*   __restrict__ self_idx,
                       const int*   __restrict__ neigh_idx,
                       float*       __restrict__ out_ext) {
    extern __shared__ float smem[];
    float2* Ws2  = (float2*)smem;                       // [2D/2][W2_STRIDE]
    float*  comb = smem + 2 * (2 * D / 2) * W2_STRIDE;  // [TM][2D]

    const float* feats = (LAYER == 1) ? feats_in : g_h1;
    float*       out   = (LAYER == 1) ? g_h1 : out_ext;

    const int t    = threadIdx.x;
    const int lane = t & 31;
    const int warp = t >> 5;                            // 8 warps, 8 rows each

    // ---- stage W as d-pair-interleaved transpose:
    //      Ws2[d/2][j] = { W[j][d], W[j][d+1] }
    {
        const float4* src = (const float4*)Wg;          // W[j][d], row j = 64 float4
        #pragma unroll
        for (int i = 0; i < (2 * D * D) / 4 / NTHREADS; i++) {
            int idx = i * NTHREADS + t;
            int j   = idx >> 6;                         // 0..127
            int d4  = idx & 63;                         // float4 within row: d = 4*d4
            float4 v = src[idx];
            Ws2[(2 * d4 + 0) * W2_STRIDE + j] = make_float2(v.x, v.y);
            Ws2[(2 * d4 + 1) * W2_STRIDE + j] = make_float2(v.z, v.w);
        }
    }
    __syncthreads();

    // ---- per-warp gather: comb slab [8][256] = [self(128)|mean_agg(128)] ----
    float* cwarp = comb + warp * 8 * (2 * D);
    {
        #pragma unroll 2
        for (int r = 0; r < 8; r++) {
            const int row  = blockIdx.x * TM + warp * 8 + r;
            const int nsel = __ldg(&self_idx[row]);
            float4 s = __ldg((const float4*)&feats[(size_t)nsel * D] + lane);
            float4 a = make_float4(0.f, 0.f, 0.f, 0.f);
            #pragma unroll
            for (int k = 0; k < KNB; k++) {
                const int nk = __ldg(&neigh_idx[row * KNB + k]);
                float4 f = __ldg((const float4*)&feats[(size_t)nk * D] + lane);
                a.x += f.x; a.y += f.y; a.z += f.z; a.w += f.w;
            }
            const float inv = 1.0f / (float)KNB;
            a.x *= inv; a.y *= inv; a.z *= inv; a.w *= inv;
            *(float4*)&cwarp[r * (2 * D) + 4 * lane]     = s;
            *(float4*)&cwarp[r * (2 * D) + D + 4 * lane] = a;
        }
    }
    __syncwarp();

    // ---- warp-local GEMM with packed f32x2 FMAs.
    //      acc2[r][c] holds (even-d partial, odd-d partial); lo+hi at the end.
    unsigned long long acc2[8][4];
    #pragma unroll
    for (int r = 0; r < 8; r++)
        #pragma unroll
        for (int c = 0; c < 4; c++) acc2[r][c] = 0ull;

    const int c0 = 4 * lane;                            // this thread's first col

    #pragma unroll 2
    for (int d2 = 0; d2 < D; d2++) {                    // 128 d-pairs
        // W pairs for this thread's 4 columns: two 16-B loads
        const ulonglong2 wv0 =
            *(const ulonglong2*)&Ws2[d2 * W2_STRIDE + c0];     // pairs c0,c0+1
        const ulonglong2 wv1 =
            *(const ulonglong2*)&Ws2[d2 * W2_STRIDE + c0 + 2]; // pairs c0+2,c0+3
        #pragma unroll
        for (int r = 0; r < 8; r++) {
            // broadcast 8-B load: (comb[d], comb[d+1])
            const unsigned long long cp =
                *(const unsigned long long*)&cwarp[r * (2 * D) + 2 * d2];
            fma_f32x2(acc2[r][0], cp, wv0.x);
            fma_f32x2(acc2[r][1], cp, wv0.y);
            fma_f32x2(acc2[r][2], cp, wv1.x);
            fma_f32x2(acc2[r][3], cp, wv1.y);
        }
    }

    // ---- epilogue: combine halves, ReLU, coalesced float4 store ----
    #pragma unroll
    for (int r = 0; r < 8; r++) {
        const int row = blockIdx.x * TM + warp * 8 + r;
        float v[4];
        #pragma unroll
        for (int c = 0; c < 4; c++) {
            float lo = __uint_as_float((unsigned)(acc2[r][c] & 0xffffffffull));
            float hi = __uint_as_float((unsigned)(acc2[r][c] >> 32));
            v[c] = fmaxf(lo + hi, 0.0f);
        }
        *(float4*)&out[(size_t)row * D + c0] = make_float4(v[0], v[1], v[2], v[3]);
    }
}

// ---------------- launch ----------------
extern "C" void kernel_launch(void* const* d_in, const int* in_sizes, int n_in,
                              void* d_out, int out_size) {
    const float* raw_features = (const float*)d_in[0];
    const float* W1           = (const float*)d_in[1];
    const float* W2           = (const float*)d_in[2];
    const int*   layer1_nodes = (const int*)d_in[3];
    const int*   neigh0_idx   = (const int*)d_in[4];
    const int*   map_batch    = (const int*)d_in[5];
    const int*   neigh1_idx   = (const int*)d_in[6];
    float*       out          = (float*)d_out;

    const int smem_bytes =
        (2 * D * W2_STRIDE + TM * 2 * D) * (int)sizeof(float);  // ~197 KB
    cudaFuncSetAttribute(sage_layer_kernel<1>,
                         cudaFuncAttributeMaxDynamicSharedMemorySize, smem_bytes);
    cudaFuncSetAttribute(sage_layer_kernel<2>,
                         cudaFuncAttributeMaxDynamicSharedMemorySize, smem_bytes);

    sage_layer_kernel<1><<<N1 / TM, NTHREADS, smem_bytes>>>(
        raw_features, W1, layer1_nodes, neigh0_idx, nullptr);
    sage_layer_kernel<2><<<BATCH / TM, NTHREADS, smem_bytes>>>(
        nullptr, W2, map_batch, neigh1_idx, out);
}

// round 7
// speedup vs baseline: 2.5685x; 1.3561x over previous
#include <cuda_runtime.h>
#include <cuda_bf16.h>
#include <cstdint>

#define D        128
#define N1       81920
#define BATCH    8192
#define KNB      10
#define TM       128        // rows per block (M)
#define NTHREADS 256
#define KPAD     136        // padded k-stride in bf16 elems (272 B rows)
#define ROWB     (KPAD * 2) // 272 bytes per row

// ---------------- device-global scratch (allocation-free rule) ----------------
__device__ float g_h1[(size_t)N1 * D];                 // layer-1 embeddings
// pre-split W: [layer][phase][hi/lo][128 n][KPAD k] bf16, padded for ldmatrix
__device__ __nv_bfloat16 g_B[2][2][2][128 * KPAD];

// ---------------- smem layout ----------------
#define OFF_A0H  0                        // self hi  [128][KPAD] bf16 = 34816 B
#define OFF_A0L  34816                    // self lo
#define OFF_A1H  69632                    // agg  hi
#define OFF_A1L  104448                   // agg  lo
#define OFF_BH   139264                   // W half hi [128 n][KPAD]
#define OFF_BL   174080                   // W half lo
#define SMEM_TOTAL 208896                 // ~204 KB

// ---------------- PTX helpers ----------------
__device__ __forceinline__ uint32_t smem_u32(const void* p) {
    uint32_t a;
    asm("{ .reg .u64 t; cvta.to.shared.u64 t, %1; cvt.u32.u64 %0, t; }"
        : "=r"(a) : "l"(p));
    return a;
}
#define LDSM4(r, addr)                                                       \
    asm volatile("ldmatrix.sync.aligned.m8n8.x4.shared.b16 {%0,%1,%2,%3}, [%4];" \
                 : "=r"((r)[0]), "=r"((r)[1]), "=r"((r)[2]), "=r"((r)[3])    \
                 : "r"(addr))
#define MMA16816(c, a, b0, b1)                                               \
    asm volatile("mma.sync.aligned.m16n8k16.row.col.f32.bf16.bf16.f32 "      \
                 "{%0,%1,%2,%3}, {%4,%5,%6,%7}, {%8,%9}, {%0,%1,%2,%3};"     \
                 : "+f"((c)[0]), "+f"((c)[1]), "+f"((c)[2]), "+f"((c)[3])    \
                 : "r"((a)[0]), "r"((a)[1]), "r"((a)[2]), "r"((a)[3]),       \
                   "r"(b0), "r"(b1))

__device__ __forceinline__ uint32_t pack_bf2(float a, float b) {
    __nv_bfloat16 ha = __float2bfloat16_rn(a), hb = __float2bfloat16_rn(b);
    return (uint32_t)__bfloat16_as_ushort(ha) |
           ((uint32_t)__bfloat16_as_ushort(hb) << 16);
}
// split float4 into bf16 hi + bf16 residual lo; 8-B store each
__device__ __forceinline__ void split_store(char* hi_p, char* lo_p, float4 v) {
    __nv_bfloat16 hx = __float2bfloat16_rn(v.x), hy = __float2bfloat16_rn(v.y);
    __nv_bfloat16 hz = __float2bfloat16_rn(v.z), hw = __float2bfloat16_rn(v.w);
    uint2 hv, lv;
    hv.x = (uint32_t)__bfloat16_as_ushort(hx) | ((uint32_t)__bfloat16_as_ushort(hy) << 16);
    hv.y = (uint32_t)__bfloat16_as_ushort(hz) | ((uint32_t)__bfloat16_as_ushort(hw) << 16);
    lv.x = pack_bf2(v.x - __bfloat162float(hx), v.y - __bfloat162float(hy));
    lv.y = pack_bf2(v.z - __bfloat162float(hz), v.w - __bfloat162float(hw));
    *(uint2*)hi_p = hv;
    *(uint2*)lo_p = lv;
}

// ---------------- prep: split W into bf16 hi/lo, padded [n][k] ----------------
__global__ void prep_w_kernel(const float* __restrict__ W1,
                              const float* __restrict__ W2) {
    for (int i = blockIdx.x * blockDim.x + threadIdx.x; i < 2 * 128 * 256;
         i += gridDim.x * blockDim.x) {
        int layer = i >> 15;
        int rem   = i & 32767;
        int j     = rem >> 8;            // output col (n)
        int d     = rem & 255;           // input dim
        const float* W = layer ? W2 : W1;
        float x = W[j * 256 + d];
        __nv_bfloat16 hi = __float2bfloat16_rn(x);
        __nv_bfloat16 lo = __float2bfloat16_rn(x - __bfloat162float(hi));
        int phase = d >> 7, k = d & 127;
        g_B[layer][phase][0][j * KPAD + k] = hi;
        g_B[layer][phase][1][j * KPAD + k] = lo;
    }
}

// one K=128 phase of the split GEMM: acc += Ah*Bh + Al*Bh + Ah*Bl
__device__ __forceinline__ void mma_phase(uint32_t aH, uint32_t aL,
                                          uint32_t bH, uint32_t bL,
                                          int lane, float acc[2][8][4]) {
    // ldmatrix lane address offsets (bytes, relative to tile base)
    const uint32_t pa = (uint32_t)((lane & 15) * ROWB + (lane >> 4) * 16);
    const uint32_t pb = (uint32_t)(((lane & 7) + ((lane >> 4) << 3)) * ROWB +
                                   ((lane >> 3) & 1) * 16);
    #pragma unroll
    for (int ks = 0; ks < 8; ks++) {
        const uint32_t ko = ks * 32;
        uint32_t ah[2][4], al[2][4], bh[4][4], bl[4][4];
        #pragma unroll
        for (int mt = 0; mt < 2; mt++) {
            LDSM4(ah[mt], aH + pa + mt * 16 * ROWB + ko);
            LDSM4(al[mt], aL + pa + mt * 16 * ROWB + ko);
        }
        #pragma unroll
        for (int nq = 0; nq < 4; nq++) {
            LDSM4(bh[nq], bH + pb + nq * 16 * ROWB + ko);
            LDSM4(bl[nq], bL + pb + nq * 16 * ROWB + ko);
        }
        #pragma unroll
        for (int mt = 0; mt < 2; mt++)
            #pragma unroll
            for (int nq = 0; nq < 4; nq++) {
                MMA16816(acc[mt][nq * 2 + 0], ah[mt], bh[nq][0], bh[nq][1]);
                MMA16816(acc[mt][nq * 2 + 1], ah[mt], bh[nq][2], bh[nq][3]);
                MMA16816(acc[mt][nq * 2 + 0], al[mt], bh[nq][0], bh[nq][1]);
                MMA16816(acc[mt][nq * 2 + 1], al[mt], bh[nq][2], bh[nq][3]);
                MMA16816(acc[mt][nq * 2 + 0], ah[mt], bl[nq][0], bl[nq][1]);
                MMA16816(acc[mt][nq * 2 + 1], ah[mt], bl[nq][2], bl[nq][3]);
            }
    }
}

// ---------------- fused SAGE layer: gather + split + HMMA + ReLU --------------
template <int LAYER>
__global__ __launch_bounds__(NTHREADS, 1)
void sage_mma_kernel(const float* __restrict__ feats_in,
                     const int*   __restrict__ self_idx,
                     const int*   __restrict__ neigh_idx,
                     float*       __restrict__ out_ext) {
    extern __shared__ char smem[];
    const uint32_t sb = smem_u32(smem);
    const int t = threadIdx.x, lane = t & 31, wid = t >> 5;

    const float* feats = (LAYER == 1) ? feats_in : g_h1;
    float*       out   = (LAYER == 1) ? g_h1 : out_ext;

    // ---- stage B phase 0 (hi+lo, 68 KB linear copy) ----
    {
        const uint4* src = (const uint4*)&g_B[LAYER - 1][0][0][0];
        uint4*       dst = (uint4*)(smem + OFF_BH);
        #pragma unroll
        for (int i = 0; i < 17; i++) dst[i * NTHREADS + t] = src[i * NTHREADS + t];
    }

    // ---- gather: 16 rows/warp; split self->A0, mean-agg->A1 (hi+lo) ----
    {
        #pragma unroll 2
        for (int rr = 0; rr < 16; rr++) {
            const int r    = wid * 16 + rr;
            const int row  = blockIdx.x * TM + r;
            const int nsel = __ldg(&self_idx[row]);
            float4 s = __ldg((const float4*)&feats[(size_t)nsel * D] + lane);
            float4 a = make_float4(0.f, 0.f, 0.f, 0.f);
            #pragma unroll
            for (int k = 0; k < KNB; k++) {
                const int nk = __ldg(&neigh_idx[row * KNB + k]);
                float4 f = __ldg((const float4*)&feats[(size_t)nk * D] + lane);
                a.x += f.x; a.y += f.y; a.z += f.z; a.w += f.w;
            }
            const float inv = 1.0f / (float)KNB;
            a.x *= inv; a.y *= inv; a.z *= inv; a.w *= inv;
            const int so = r * ROWB + lane * 8;
            split_store(smem + OFF_A0H + so, smem + OFF_A0L + so, s);
            split_store(smem + OFF_A1H + so, smem + OFF_A1L + so, a);
        }
    }
    __syncthreads();

    // ---- warp tiling: 4(m) x 2(n); each warp owns 32 x 64 output ----
    const int wm = wid & 3, wn = wid >> 2;
    const uint32_t aoff = (uint32_t)(wm * 32 * ROWB);
    const uint32_t boff = (uint32_t)(wn * 64 * ROWB);

    float acc[2][8][4];
    #pragma unroll
    for (int mt = 0; mt < 2; mt++)
        #pragma unroll
        for (int nt = 0; nt < 8; nt++)
            #pragma unroll
            for (int c = 0; c < 4; c++) acc[mt][nt][c] = 0.0f;

    // ---- phase 0: self features x W[:, 0:128] ----
    mma_phase(sb + OFF_A0H + aoff, sb + OFF_A0L + aoff,
              sb + OFF_BH + boff,  sb + OFF_BL + boff, lane, acc);

    // ---- restage B for phase 1 ----
    __syncthreads();
    {
        const uint4* src = (const uint4*)&g_B[LAYER - 1][1][0][0];
        uint4*       dst = (uint4*)(smem + OFF_BH);
        #pragma unroll
        for (int i = 0; i < 17; i++) dst[i * NTHREADS + t] = src[i * NTHREADS + t];
    }
    __syncthreads();

    // ---- phase 1: agg features x W[:, 128:256] ----
    mma_phase(sb + OFF_A1H + aoff, sb + OFF_A1L + aoff,
              sb + OFF_BH + boff,  sb + OFF_BL + boff, lane, acc);

    // ---- epilogue: ReLU + float2 stores ----
    const int rb = blockIdx.x * TM + wm * 32 + (lane >> 2);
    const int cb = wn * 64 + (lane & 3) * 2;
    #pragma unroll
    for (int mt = 0; mt < 2; mt++)
        #pragma unroll
        for (int nt = 0; nt < 8; nt++) {
            const int row = rb + mt * 16;
            const int col = cb + nt * 8;
            float2 v0 = make_float2(fmaxf(acc[mt][nt][0], 0.f),
                                    fmaxf(acc[mt][nt][1], 0.f));
            float2 v1 = make_float2(fmaxf(acc[mt][nt][2], 0.f),
                                    fmaxf(acc[mt][nt][3], 0.f));
            *(float2*)&out[(size_t)row * D + col]       = v0;
            *(float2*)&out[(size_t)(row + 8) * D + col] = v1;
        }
}

// ---------------- launch ----------------
extern "C" void kernel_launch(void* const* d_in, const int* in_sizes, int n_in,
                              void* d_out, int out_size) {
    const float* raw_features = (const float*)d_in[0];
    const float* W1           = (const float*)d_in[1];
    const float* W2           = (const float*)d_in[2];
    const int*   layer1_nodes = (const int*)d_in[3];
    const int*   neigh0_idx   = (const int*)d_in[4];
    const int*   map_batch    = (const int*)d_in[5];
    const int*   neigh1_idx   = (const int*)d_in[6];
    float*       out          = (float*)d_out;

    cudaFuncSetAttribute(sage_mma_kernel<1>,
                         cudaFuncAttributeMaxDynamicSharedMemorySize, SMEM_TOTAL);
    cudaFuncSetAttribute(sage_mma_kernel<2>,
                         cudaFuncAttributeMaxDynamicSharedMemorySize, SMEM_TOTAL);

    prep_w_kernel<<<64, NTHREADS>>>(W1, W2);
    sage_mma_kernel<1><<<N1 / TM, NTHREADS, SMEM_TOTAL>>>(
        raw_features, layer1_nodes, neigh0_idx, nullptr);
    sage_mma_kernel<2><<<BATCH / TM, NTHREADS, SMEM_TOTAL>>>(
        nullptr, map_batch, neigh1_idx, out);
}